// round 12
// baseline (speedup 1.0000x reference)
#include <cuda_runtime.h>
#include <cuda_fp16.h>
#include <cstdint>
#include <math.h>

// ---------------- problem constants ----------------
#define Bn  4
#define Sn  8192
#define Dn  1024
#define SDn 512
#define Mn  (Bn * Sn)          // 32768 rows
#define TS  128                // scan tile (rows) == BM
#define NT  (Sn / TS)          // 64 tiles per batch
#define RMS_EPS 1.1920929e-07f

// ---------------- GEMM tiling (fp16 operands) ----------------
#define BM 128
#define BN 128
#define THR 128                              // 4 warps: grid 2(M) x 2(N), tile 64x64
#define BKH 64                               // K halves per stage (128 B rows)
#define STAGES 3
#define SROWH 72                             // padded halves per row (64+8) -> 144 B
#define ROWB (SROWH * 2)                     // 144 bytes
#define STAGE_BYTES ((BM + BN) * ROWB)       // 36864 B
#define SMEM_BYTES  (STAGES * STAGE_BYTES)   // 110592 B (2 CTAs/SM)

// ---------------- scratch ----------------
__device__ __align__(128) __half g_xh[Mn * Dn];       // x, fp16
__device__ __align__(128) __half g_wb[2 * SDn * Dn];  // interleaved Wg/Wu rows, fp16
__device__ __align__(128) __half g_wo[Dn * SDn];      // W_out fp16
__device__ __align__(128) __half g_zh[Mn * SDn];      // z then h (fp16, in place)
__device__ __align__(128) float  g_tilesum[(Mn / TS) * SDn];
__device__ __align__(128) float  g_rmsinv[Mn];

// ---------------- helpers ----------------
__device__ __forceinline__ uint32_t smem_u32(const void* p) {
    uint32_t a;
    asm("{ .reg .u64 t; cvta.to.shared.u64 t, %1; cvt.u32.u64 %0, t; }" : "=r"(a) : "l"(p));
    return a;
}
__device__ __forceinline__ void cp16(uint32_t d, const void* s) {
    asm volatile("cp.async.cg.shared.global [%0], [%1], 16;" :: "r"(d), "l"(s));
}
#define CP_COMMIT() asm volatile("cp.async.commit_group;" ::: "memory")
#define CP_WAIT(n)  asm volatile("cp.async.wait_group %0;" :: "n"(n) : "memory")

__device__ __forceinline__ void mma_f16(float* c, const uint32_t* a, uint32_t b0, uint32_t b1) {
    asm volatile(
        "mma.sync.aligned.m16n8k16.row.col.f32.f16.f16.f32 "
        "{%0,%1,%2,%3}, {%4,%5,%6,%7}, {%8,%9}, {%0,%1,%2,%3};"
        : "+f"(c[0]), "+f"(c[1]), "+f"(c[2]), "+f"(c[3])
        : "r"(a[0]), "r"(a[1]), "r"(a[2]), "r"(a[3]), "r"(b0), "r"(b1));
}
__device__ __forceinline__ void ldsm4(uint32_t& r0, uint32_t& r1, uint32_t& r2, uint32_t& r3,
                                      uint32_t addr) {
    asm volatile("ldmatrix.sync.aligned.m8n8.x4.shared.b16 {%0,%1,%2,%3}, [%4];"
        : "=r"(r0), "=r"(r1), "=r"(r2), "=r"(r3) : "r"(addr));
}
__device__ __forceinline__ float sigmoidf_fast(float g) {
    return 1.0f / (1.0f + __expf(-g));
}

// ===========================================================================
// conversion kernels: fp32 -> fp16 (RN)
// ===========================================================================
__global__ void k_cvt_h(const float4* __restrict__ src, __half2* __restrict__ dst, int n4) {
    for (int i = blockIdx.x * blockDim.x + threadIdx.x; i < n4; i += gridDim.x * blockDim.x) {
        float4 v = src[i];
        dst[2 * i]     = __floats2half2_rn(v.x, v.y);
        dst[2 * i + 1] = __floats2half2_rn(v.z, v.w);
    }
}
__global__ void k_cvt_pair_h(const float4* __restrict__ wg, const float4* __restrict__ wu,
                             __half2* __restrict__ dst) {
    const int RW = Dn / 4;
    const int total = SDn * RW;
    for (int i = blockIdx.x * blockDim.x + threadIdx.x; i < total; i += gridDim.x * blockDim.x) {
        int r = i / RW, c = i % RW;
        float4 vg = wg[i];
        float4 vu = wu[i];
        size_t dg = (size_t)(2 * r) * (Dn / 2) + 2 * c;
        size_t du = (size_t)(2 * r + 1) * (Dn / 2) + 2 * c;
        dst[dg]     = __floats2half2_rn(vg.x, vg.y);
        dst[dg + 1] = __floats2half2_rn(vg.z, vg.w);
        dst[du]     = __floats2half2_rn(vu.x, vu.y);
        dst[du + 1] = __floats2half2_rn(vu.z, vu.w);
    }
}

// ===========================================================================
// fp16 GEMM mainloop. A: [M x K] rm halves, B: [N x K] rm halves (C = A@B^T).
// CTA tile 128x128, 128 threads, warp grid 2(M) x 2(N), warp tile 64x64.
// A dup x2, B dup x2 -> 64KB LDSM/iter (crossbar relief) AND 2 CTAs/SM.
// ===========================================================================
struct Frag { float acc[4][8][4]; };

template<int KTOT>
__device__ __forceinline__ void gemm_mainloop(const __half* __restrict__ A,
                                              const __half* __restrict__ B,
                                              int m0, int n0, char* smem, Frag& f) {
    const int t = threadIdx.x;
    const uint32_t sb0 = smem_u32(smem);
    const int lrow = t >> 3;          // 0..15
    const int lseg = t & 7;           // 16B chunk (8 halves) within 128B row

    const int iters = KTOT / BKH;

    #pragma unroll
    for (int i = 0; i < 4; i++)
        #pragma unroll
        for (int j = 0; j < 8; j++)
            #pragma unroll
            for (int q = 0; q < 4; q++) f.acc[i][j][q] = 0.f;

    // stage loader: 16 chunks/thread (i<8 -> A rows 0..127, i>=8 -> B rows 0..127)
    #pragma unroll
    for (int p = 0; p < STAGES - 1; p++) {
        const int k0 = p * BKH;
        #pragma unroll
        for (int i = 0; i < 16; i++) {
            if (i < 8) {
                const int row = 16 * i + lrow;
                cp16(sb0 + p * STAGE_BYTES + row * ROWB + lseg * 16,
                     A + (size_t)(m0 + row) * KTOT + k0 + lseg * 8);
            } else {
                const int row = 16 * (i - 8) + lrow;
                cp16(sb0 + p * STAGE_BYTES + (BM + row) * ROWB + lseg * 16,
                     B + (size_t)(n0 + row) * KTOT + k0 + lseg * 8);
            }
        }
        CP_COMMIT();
    }

    const int wid = t >> 5, lane = t & 31;
    const int wm = wid & 1, wn = wid >> 1;
    const int mrow = wm * 64, nb = wn * 64;

    const uint32_t arow = ((lane >> 3) & 1) * 8 + (lane & 7);
    const uint32_t acolb = ((lane >> 4) & 1) * 16;
    const uint32_t a_off = (mrow + arow) * ROWB + acolb;
    const uint32_t brow = ((lane >> 4) & 1) * 8 + (lane & 7);
    const uint32_t bcolb = ((lane >> 3) & 1) * 16;
    const uint32_t b_off = (BM + nb + brow) * ROWB + bcolb;

    int rs = 0;
    for (int it = 0; it < iters; it++) {
        CP_WAIT(STAGES - 2);
        __syncthreads();

        if (it + STAGES - 1 < iters) {
            int ws = rs + STAGES - 1; if (ws >= STAGES) ws -= STAGES;
            const int k0 = (it + STAGES - 1) * BKH;
            #pragma unroll
            for (int i = 0; i < 16; i++) {
                if (i < 8) {
                    const int row = 16 * i + lrow;
                    cp16(sb0 + ws * STAGE_BYTES + row * ROWB + lseg * 16,
                         A + (size_t)(m0 + row) * KTOT + k0 + lseg * 8);
                } else {
                    const int row = 16 * (i - 8) + lrow;
                    cp16(sb0 + ws * STAGE_BYTES + (BM + row) * ROWB + lseg * 16,
                         B + (size_t)(n0 + row) * KTOT + k0 + lseg * 8);
                }
            }
        }
        CP_COMMIT();

        const uint32_t sbase = sb0 + rs * STAGE_BYTES;

        #pragma unroll
        for (int s = 0; s < BKH / 16; s++) {      // 4 k16-steps
            const uint32_t ko = s * 32;
            uint32_t a[4][4];
            #pragma unroll
            for (int mt = 0; mt < 4; mt++)
                ldsm4(a[mt][0], a[mt][1], a[mt][2], a[mt][3],
                      sbase + a_off + mt * 16 * ROWB + ko);
            uint32_t b[8][2];
            #pragma unroll
            for (int p = 0; p < 4; p++)
                ldsm4(b[2*p][0], b[2*p][1], b[2*p+1][0], b[2*p+1][1],
                      sbase + b_off + p * 16 * ROWB + ko);
            #pragma unroll
            for (int nt = 0; nt < 8; nt++)
                #pragma unroll
                for (int mt = 0; mt < 4; mt++)
                    mma_f16(f.acc[mt][nt], a[mt], b[nt][0], b[nt][1]);
        }
        rs++; if (rs == STAGES) rs = 0;
    }
    __syncthreads();
}

// ===========================================================================
// k1: C = x @ Wb^T. Epilogue: z = sigmoid(g)*u rounded to fp16 -> g_zh,
// per-CTA 128-row tile column sums (64 z-cols) from the ROUNDED values.
// ===========================================================================
__global__ void __launch_bounds__(THR, 2) k1_gemm() {
    extern __shared__ char smem[];
    const int n0 = blockIdx.x * BN;
    const int m0 = blockIdx.y * BM;
    Frag f;
    gemm_mainloop<Dn>(g_xh, g_wb, m0, n0, smem, f);

    const int t = threadIdx.x;
    const int wid = t >> 5, lane = t & 31;
    const int wm = wid & 1, wn = wid >> 1;
    const int gr = lane >> 2, gc = lane & 3;
    const int zbase = n0 >> 1;             // 64 z-cols per CTA

    float* csum = (float*)smem;
    if (t < 64) csum[t] = 0.f;
    __syncthreads();

    #pragma unroll
    for (int nt = 0; nt < 8; nt++) {
        float cs = 0.f;
        #pragma unroll
        for (int mt = 0; mt < 4; mt++) {
            const int r0 = m0 + wm * 64 + mt * 16 + gr;
            const int zc = zbase + wn * 32 + nt * 4 + gc;
            __half h0 = __float2half_rn(f.acc[mt][nt][1] * sigmoidf_fast(f.acc[mt][nt][0]));
            __half h1 = __float2half_rn(f.acc[mt][nt][3] * sigmoidf_fast(f.acc[mt][nt][2]));
            g_zh[(size_t)r0 * SDn + zc] = h0;
            g_zh[(size_t)(r0 + 8) * SDn + zc] = h1;
            cs += __half2float(h0) + __half2float(h1);
        }
        cs += __shfl_xor_sync(0xffffffffu, cs, 4);
        cs += __shfl_xor_sync(0xffffffffu, cs, 8);
        cs += __shfl_xor_sync(0xffffffffu, cs, 16);
        if (gr == 0)
            atomicAdd(&csum[wn * 32 + nt * 4 + gc], cs);
    }
    __syncthreads();
    if (t < 64)
        g_tilesum[(size_t)blockIdx.y * SDn + zbase + t] = csum[t];
}

// ===========================================================================
// k2: exclusive prefix over tiles per (b,k) channel (register-batched loads)
// ===========================================================================
__global__ void k2_tileprefix() {
    const int idx = blockIdx.x * blockDim.x + threadIdx.x;
    const size_t base = (size_t)(idx / SDn) * NT * SDn + (idx % SDn);
    float v[NT];
    #pragma unroll
    for (int t = 0; t < NT; t++) v[t] = g_tilesum[base + (size_t)t * SDn];
    float run = 0.f;
    #pragma unroll
    for (int t = 0; t < NT; t++) {
        float nv = run + v[t];
        g_tilesum[base + (size_t)t * SDn] = run;
        run = nv;
    }
}

// ===========================================================================
// k3a: pure streaming scan in place on g_zh (fp16). grid (2, 256) x 128 thr
// (512 blocks for wave balance), each thread one half2 column of one tile.
// ===========================================================================
__global__ void __launch_bounds__(128) k3a_scan() {
    const int mt = blockIdx.y;
    const int t = mt & (NT - 1);
    const int k2i = blockIdx.x * 128 + threadIdx.x;   // half2 column (0..255)
    const int base = mt * TS;

    const float2 ts = *(const float2*)&g_tilesum[(size_t)mt * SDn + 2 * k2i];
    float c0 = ts.x, c1 = ts.y;

    __half2* zp = (__half2*)g_zh + ((size_t)base * SDn >> 1) + k2i;

    #pragma unroll 8
    for (int r = 0; r < TS; r++) {
        float2 zv = __half22float2(zp[0]);
        c0 += zv.x;
        c1 += zv.y;
        const float inv = __frcp_rn((float)(t * TS + r + 1));
        zp[0] = __floats2half2_rn(c0 * inv, c1 * inv);
        zp += SDn / 2;
    }
}

// ===========================================================================
// k_rms: per-row rms_inv from fp16 h. Warp per row, 8 rows per block.
// ===========================================================================
__global__ void __launch_bounds__(256) k_rms() {
    const int row = blockIdx.x * 8 + (threadIdx.x >> 5);
    const int lane = threadIdx.x & 31;
    const uint4* p = (const uint4*)(g_zh + (size_t)row * SDn);

    float s = 0.f;
    #pragma unroll
    for (int i = 0; i < 2; i++) {
        uint4 v = p[lane + 32 * i];
        float2 a0 = __half22float2(*(__half2*)&v.x);
        float2 a1 = __half22float2(*(__half2*)&v.y);
        float2 a2 = __half22float2(*(__half2*)&v.z);
        float2 a3 = __half22float2(*(__half2*)&v.w);
        s += a0.x*a0.x + a0.y*a0.y + a1.x*a1.x + a1.y*a1.y
           + a2.x*a2.x + a2.y*a2.y + a3.x*a3.x + a3.y*a3.y;
    }
    #pragma unroll
    for (int o = 16; o > 0; o >>= 1) s += __shfl_xor_sync(0xffffffffu, s, o);
    if (lane == 0)
        g_rmsinv[row] = rsqrtf(s * (1.0f / SDn) + RMS_EPS);
}

// ===========================================================================
// k3b: out = rms_inv[m] * (h @ Wo^T), M=32768, N=1024, K=512 (fp16 inputs)
// ===========================================================================
__global__ void __launch_bounds__(THR, 2) k3b_gemm(float* __restrict__ out) {
    extern __shared__ char smem[];
    const int n0 = blockIdx.x * BN;
    const int m0 = blockIdx.y * BM;
    Frag f;
    gemm_mainloop<SDn>(g_zh, g_wo, m0, n0, smem, f);

    const int t = threadIdx.x;
    const int wid = t >> 5, lane = t & 31;
    const int wm = wid & 1, wn = wid >> 1;
    const int gr = lane >> 2, gc = lane & 3;

    #pragma unroll
    for (int mt = 0; mt < 4; mt++) {
        const int r0 = m0 + wm * 64 + mt * 16 + gr;
        const float ri0 = g_rmsinv[r0];
        const float ri1 = g_rmsinv[r0 + 8];
        #pragma unroll
        for (int nt = 0; nt < 8; nt++) {
            const int col = n0 + wn * 64 + nt * 8 + gc * 2;
            float2 v0 = { f.acc[mt][nt][0] * ri0, f.acc[mt][nt][1] * ri0 };
            float2 v1 = { f.acc[mt][nt][2] * ri1, f.acc[mt][nt][3] * ri1 };
            *(float2*)&out[(size_t)r0 * Dn + col] = v0;
            *(float2*)&out[(size_t)(r0 + 8) * Dn + col] = v1;
        }
    }
}

// ===========================================================================
// host side
// ===========================================================================
extern "C" void kernel_launch(void* const* d_in, const int* in_sizes, int n_in,
                              void* d_out, int out_size) {
    const float* x  = (const float*)d_in[0];
    const float* Wu = (const float*)d_in[1];
    const float* Wg = (const float*)d_in[2];
    const float* Wo = (const float*)d_in[3];
    float* out = (float*)d_out;

    void *pxh, *pwb, *pwo;
    cudaGetSymbolAddress(&pxh, g_xh);
    cudaGetSymbolAddress(&pwb, g_wb);
    cudaGetSymbolAddress(&pwo, g_wo);

    cudaFuncSetAttribute(k1_gemm,  cudaFuncAttributeMaxDynamicSharedMemorySize, SMEM_BYTES);
    cudaFuncSetAttribute(k3b_gemm, cudaFuncAttributeMaxDynamicSharedMemorySize, SMEM_BYTES);

    k_cvt_h<<<4096, 256>>>((const float4*)x, (__half2*)pxh, Mn * Dn / 4);
    k_cvt_pair_h<<<512, 256>>>((const float4*)Wg, (const float4*)Wu, (__half2*)pwb);
    k_cvt_h<<<512, 256>>>((const float4*)Wo, (__half2*)pwo, Dn * SDn / 4);

    k1_gemm<<<dim3(2 * SDn / BN, Mn / BM), THR, SMEM_BYTES>>>();
    k2_tileprefix<<<(Bn * SDn) / 256, 256>>>();
    k3a_scan<<<dim3(2, Mn / TS), 128>>>();
    k_rms<<<Mn / 8, 256>>>();
    k3b_gemm<<<dim3(Dn / BN, Mn / BM), THR, SMEM_BYTES>>>(out);
}

// round 14
// speedup vs baseline: 1.0122x; 1.0122x over previous
#include <cuda_runtime.h>
#include <cuda_fp16.h>
#include <cstdint>
#include <math.h>

// ---------------- problem constants ----------------
#define Bn  4
#define Sn  8192
#define Dn  1024
#define SDn 512
#define Mn  (Bn * Sn)          // 32768 rows
#define TS  128                // scan tile (rows) == BM
#define NT  (Sn / TS)          // 64 tiles per batch
#define RMS_EPS 1.1920929e-07f

// ---------------- GEMM tiling (fp16 operands) ----------------
#define BM 128
#define BN 128
#define THR 128                              // 4 warps: grid 2(M) x 2(N), tile 64x64
#define BKH 64                               // K halves per stage (128 B rows)
#define STAGES 3
#define SROWH 72                             // padded halves per row (64+8) -> 144 B
#define ROWB (SROWH * 2)                     // 144 bytes
#define STAGE_BYTES ((BM + BN) * ROWB)       // 36864 B
#define SMEM_BYTES  (STAGES * STAGE_BYTES)   // 110592 B (2 CTAs/SM)

// ---------------- scratch ----------------
__device__ __align__(128) __half g_xh[Mn * Dn];       // x, fp16
__device__ __align__(128) __half g_wb[2 * SDn * Dn];  // interleaved Wg/Wu rows, fp16
__device__ __align__(128) __half g_wo[Dn * SDn];      // W_out fp16
__device__ __align__(128) __half g_zh[Mn * SDn];      // z then h (fp16, in place)
__device__ __align__(128) float  g_tilesum[(Mn / TS) * SDn];
__device__ __align__(128) float  g_rmsinv[Mn];

// ---------------- helpers ----------------
__device__ __forceinline__ uint32_t smem_u32(const void* p) {
    uint32_t a;
    asm("{ .reg .u64 t; cvta.to.shared.u64 t, %1; cvt.u32.u64 %0, t; }" : "=r"(a) : "l"(p));
    return a;
}
__device__ __forceinline__ void cp16(uint32_t d, const void* s) {
    asm volatile("cp.async.cg.shared.global [%0], [%1], 16;" :: "r"(d), "l"(s));
}
#define CP_COMMIT() asm volatile("cp.async.commit_group;" ::: "memory")
#define CP_WAIT(n)  asm volatile("cp.async.wait_group %0;" :: "n"(n) : "memory")

__device__ __forceinline__ void mma_f16(float* c, const uint32_t* a, uint32_t b0, uint32_t b1) {
    asm volatile(
        "mma.sync.aligned.m16n8k16.row.col.f32.f16.f16.f32 "
        "{%0,%1,%2,%3}, {%4,%5,%6,%7}, {%8,%9}, {%0,%1,%2,%3};"
        : "+f"(c[0]), "+f"(c[1]), "+f"(c[2]), "+f"(c[3])
        : "r"(a[0]), "r"(a[1]), "r"(a[2]), "r"(a[3]), "r"(b0), "r"(b1));
}
__device__ __forceinline__ void ldsm4(uint32_t& r0, uint32_t& r1, uint32_t& r2, uint32_t& r3,
                                      uint32_t addr) {
    asm volatile("ldmatrix.sync.aligned.m8n8.x4.shared.b16 {%0,%1,%2,%3}, [%4];"
        : "=r"(r0), "=r"(r1), "=r"(r2), "=r"(r3) : "r"(addr));
}
__device__ __forceinline__ float sigmoidf_fast(float g) {
    return 1.0f / (1.0f + __expf(-g));
}

// ===========================================================================
// k_cvt_all: one launch converts x, Wg/Wu (interleaved), Wo to fp16
// ===========================================================================
__global__ void k_cvt_all(const float4* __restrict__ x,
                          const float4* __restrict__ wg,
                          const float4* __restrict__ wu,
                          const float4* __restrict__ wo) {
    const int NX = Mn * Dn / 4;      // x float4 count
    const int NW = SDn * Dn / 4;     // per weight matrix
    const int RW = Dn / 4;
    __half2* xd = (__half2*)g_xh;
    __half2* wbd = (__half2*)g_wb;
    __half2* wod = (__half2*)g_wo;
    const int total = NX + 2 * NW;
    for (int i = blockIdx.x * blockDim.x + threadIdx.x; i < total; i += gridDim.x * blockDim.x) {
        if (i < NX) {
            float4 v = x[i];
            xd[2 * i]     = __floats2half2_rn(v.x, v.y);
            xd[2 * i + 1] = __floats2half2_rn(v.z, v.w);
        } else if (i < NX + NW) {
            const int j = i - NX;
            const int r = j / RW, c = j % RW;
            float4 vg = wg[j];
            float4 vu = wu[j];
            size_t dg = (size_t)(2 * r) * (Dn / 2) + 2 * c;
            size_t du = (size_t)(2 * r + 1) * (Dn / 2) + 2 * c;
            wbd[dg]     = __floats2half2_rn(vg.x, vg.y);
            wbd[dg + 1] = __floats2half2_rn(vg.z, vg.w);
            wbd[du]     = __floats2half2_rn(vu.x, vu.y);
            wbd[du + 1] = __floats2half2_rn(vu.z, vu.w);
        } else {
            const int j = i - NX - NW;
            float4 v = wo[j];
            wod[2 * j]     = __floats2half2_rn(v.x, v.y);
            wod[2 * j + 1] = __floats2half2_rn(v.z, v.w);
        }
    }
}

// ===========================================================================
// fp16 GEMM mainloop. CTA tile 128x128, 128 threads, warp tile 64x64.
// 2 CTAs/SM.
// ===========================================================================
struct Frag { float acc[4][8][4]; };

template<int KTOT>
__device__ __forceinline__ void gemm_mainloop(const __half* __restrict__ A,
                                              const __half* __restrict__ B,
                                              int m0, int n0, char* smem, Frag& f) {
    const int t = threadIdx.x;
    const uint32_t sb0 = smem_u32(smem);
    const int lrow = t >> 3;          // 0..15
    const int lseg = t & 7;

    const int iters = KTOT / BKH;

    #pragma unroll
    for (int i = 0; i < 4; i++)
        #pragma unroll
        for (int j = 0; j < 8; j++)
            #pragma unroll
            for (int q = 0; q < 4; q++) f.acc[i][j][q] = 0.f;

    #pragma unroll
    for (int p = 0; p < STAGES - 1; p++) {
        const int k0 = p * BKH;
        #pragma unroll
        for (int i = 0; i < 16; i++) {
            if (i < 8) {
                const int row = 16 * i + lrow;
                cp16(sb0 + p * STAGE_BYTES + row * ROWB + lseg * 16,
                     A + (size_t)(m0 + row) * KTOT + k0 + lseg * 8);
            } else {
                const int row = 16 * (i - 8) + lrow;
                cp16(sb0 + p * STAGE_BYTES + (BM + row) * ROWB + lseg * 16,
                     B + (size_t)(n0 + row) * KTOT + k0 + lseg * 8);
            }
        }
        CP_COMMIT();
    }

    const int wid = t >> 5, lane = t & 31;
    const int wm = wid & 1, wn = wid >> 1;
    const int mrow = wm * 64, nb = wn * 64;

    const uint32_t arow = ((lane >> 3) & 1) * 8 + (lane & 7);
    const uint32_t acolb = ((lane >> 4) & 1) * 16;
    const uint32_t a_off = (mrow + arow) * ROWB + acolb;
    const uint32_t brow = ((lane >> 4) & 1) * 8 + (lane & 7);
    const uint32_t bcolb = ((lane >> 3) & 1) * 16;
    const uint32_t b_off = (BM + nb + brow) * ROWB + bcolb;

    int rs = 0;
    for (int it = 0; it < iters; it++) {
        CP_WAIT(STAGES - 2);
        __syncthreads();

        if (it + STAGES - 1 < iters) {
            int ws = rs + STAGES - 1; if (ws >= STAGES) ws -= STAGES;
            const int k0 = (it + STAGES - 1) * BKH;
            #pragma unroll
            for (int i = 0; i < 16; i++) {
                if (i < 8) {
                    const int row = 16 * i + lrow;
                    cp16(sb0 + ws * STAGE_BYTES + row * ROWB + lseg * 16,
                         A + (size_t)(m0 + row) * KTOT + k0 + lseg * 8);
                } else {
                    const int row = 16 * (i - 8) + lrow;
                    cp16(sb0 + ws * STAGE_BYTES + (BM + row) * ROWB + lseg * 16,
                         B + (size_t)(n0 + row) * KTOT + k0 + lseg * 8);
                }
            }
        }
        CP_COMMIT();

        const uint32_t sbase = sb0 + rs * STAGE_BYTES;

        #pragma unroll
        for (int s = 0; s < BKH / 16; s++) {
            const uint32_t ko = s * 32;
            uint32_t a[4][4];
            #pragma unroll
            for (int mt = 0; mt < 4; mt++)
                ldsm4(a[mt][0], a[mt][1], a[mt][2], a[mt][3],
                      sbase + a_off + mt * 16 * ROWB + ko);
            uint32_t b[8][2];
            #pragma unroll
            for (int p = 0; p < 4; p++)
                ldsm4(b[2*p][0], b[2*p][1], b[2*p+1][0], b[2*p+1][1],
                      sbase + b_off + p * 16 * ROWB + ko);
            #pragma unroll
            for (int nt = 0; nt < 8; nt++)
                #pragma unroll
                for (int mt = 0; mt < 4; mt++)
                    mma_f16(f.acc[mt][nt], a[mt], b[nt][0], b[nt][1]);
        }
        rs++; if (rs == STAGES) rs = 0;
    }
    __syncthreads();
}

// ===========================================================================
// k1: C = x @ Wb^T. Epilogue: z = sigmoid(g)*u -> fp16 g_zh + tile col sums.
// ===========================================================================
__global__ void __launch_bounds__(THR, 2) k1_gemm() {
    extern __shared__ char smem[];
    const int n0 = blockIdx.x * BN;
    const int m0 = blockIdx.y * BM;
    Frag f;
    gemm_mainloop<Dn>(g_xh, g_wb, m0, n0, smem, f);

    const int t = threadIdx.x;
    const int wid = t >> 5, lane = t & 31;
    const int wm = wid & 1, wn = wid >> 1;
    const int gr = lane >> 2, gc = lane & 3;
    const int zbase = n0 >> 1;             // 64 z-cols per CTA

    float* csum = (float*)smem;
    if (t < 64) csum[t] = 0.f;
    __syncthreads();

    #pragma unroll
    for (int nt = 0; nt < 8; nt++) {
        float cs = 0.f;
        #pragma unroll
        for (int mt = 0; mt < 4; mt++) {
            const int r0 = m0 + wm * 64 + mt * 16 + gr;
            const int zc = zbase + wn * 32 + nt * 4 + gc;
            __half h0 = __float2half_rn(f.acc[mt][nt][1] * sigmoidf_fast(f.acc[mt][nt][0]));
            __half h1 = __float2half_rn(f.acc[mt][nt][3] * sigmoidf_fast(f.acc[mt][nt][2]));
            g_zh[(size_t)r0 * SDn + zc] = h0;
            g_zh[(size_t)(r0 + 8) * SDn + zc] = h1;
            cs += __half2float(h0) + __half2float(h1);
        }
        cs += __shfl_xor_sync(0xffffffffu, cs, 4);
        cs += __shfl_xor_sync(0xffffffffu, cs, 8);
        cs += __shfl_xor_sync(0xffffffffu, cs, 16);
        if (gr == 0)
            atomicAdd(&csum[wn * 32 + nt * 4 + gc], cs);
    }
    __syncthreads();
    if (t < 64)
        g_tilesum[(size_t)blockIdx.y * SDn + zbase + t] = csum[t];
}

// ===========================================================================
// k3a: scan with inline exclusive tile-prefix (k2 eliminated).
// grid (2, 256) x 128 threads; each thread one half2 column of one tile.
// ===========================================================================
__global__ void __launch_bounds__(128) k3a_scan() {
    const int mt = blockIdx.y;                         // global tile 0..255
    const int ty = mt & (NT - 1);                      // tile within batch
    const int b = mt >> 6;                             // batch
    const int k2i = blockIdx.x * 128 + threadIdx.x;    // half2 column (0..255)
    const int base = mt * TS;

    // exclusive prefix of tile sums for this channel pair
    float c0 = 0.f, c1 = 0.f;
    for (int i = 0; i < ty; i++) {
        const float2 v = *(const float2*)&g_tilesum[(size_t)(b * NT + i) * SDn + 2 * k2i];
        c0 += v.x; c1 += v.y;
    }

    __half2* zp = (__half2*)g_zh + ((size_t)base * SDn >> 1) + k2i;

    #pragma unroll 8
    for (int r = 0; r < TS; r++) {
        float2 zv = __half22float2(zp[0]);
        c0 += zv.x;
        c1 += zv.y;
        const float inv = __frcp_rn((float)(ty * TS + r + 1));
        zp[0] = __floats2half2_rn(c0 * inv, c1 * inv);
        zp += SDn / 2;
    }
}

// ===========================================================================
// k_rms: per-row rms_inv from fp16 h. Warp per row, 8 rows per block.
// ===========================================================================
__global__ void __launch_bounds__(256) k_rms() {
    const int row = blockIdx.x * 8 + (threadIdx.x >> 5);
    const int lane = threadIdx.x & 31;
    const uint4* p = (const uint4*)(g_zh + (size_t)row * SDn);

    float s = 0.f;
    #pragma unroll
    for (int i = 0; i < 2; i++) {
        uint4 v = p[lane + 32 * i];
        float2 a0 = __half22float2(*(__half2*)&v.x);
        float2 a1 = __half22float2(*(__half2*)&v.y);
        float2 a2 = __half22float2(*(__half2*)&v.z);
        float2 a3 = __half22float2(*(__half2*)&v.w);
        s += a0.x*a0.x + a0.y*a0.y + a1.x*a1.x + a1.y*a1.y
           + a2.x*a2.x + a2.y*a2.y + a3.x*a3.x + a3.y*a3.y;
    }
    #pragma unroll
    for (int o = 16; o > 0; o >>= 1) s += __shfl_xor_sync(0xffffffffu, s, o);
    if (lane == 0)
        g_rmsinv[row] = rsqrtf(s * (1.0f / SDn) + RMS_EPS);
}

// ===========================================================================
// k3b: out = rms_inv[m] * (h @ Wo^T), M=32768, N=1024, K=512 (fp16 inputs)
// ===========================================================================
__global__ void __launch_bounds__(THR, 2) k3b_gemm(float* __restrict__ out) {
    extern __shared__ char smem[];
    const int n0 = blockIdx.x * BN;
    const int m0 = blockIdx.y * BM;
    Frag f;
    gemm_mainloop<SDn>(g_zh, g_wo, m0, n0, smem, f);

    const int t = threadIdx.x;
    const int wid = t >> 5, lane = t & 31;
    const int wm = wid & 1, wn = wid >> 1;
    const int gr = lane >> 2, gc = lane & 3;

    #pragma unroll
    for (int mt = 0; mt < 4; mt++) {
        const int r0 = m0 + wm * 64 + mt * 16 + gr;
        const float ri0 = g_rmsinv[r0];
        const float ri1 = g_rmsinv[r0 + 8];
        #pragma unroll
        for (int nt = 0; nt < 8; nt++) {
            const int col = n0 + wn * 64 + nt * 8 + gc * 2;
            float2 v0 = { f.acc[mt][nt][0] * ri0, f.acc[mt][nt][1] * ri0 };
            float2 v1 = { f.acc[mt][nt][2] * ri1, f.acc[mt][nt][3] * ri1 };
            *(float2*)&out[(size_t)r0 * Dn + col] = v0;
            *(float2*)&out[(size_t)(r0 + 8) * Dn + col] = v1;
        }
    }
}

// ===========================================================================
// host side — single stream, no runtime allocation of any kind
// ===========================================================================
extern "C" void kernel_launch(void* const* d_in, const int* in_sizes, int n_in,
                              void* d_out, int out_size) {
    const float* x  = (const float*)d_in[0];
    const float* Wu = (const float*)d_in[1];
    const float* Wg = (const float*)d_in[2];
    const float* Wo = (const float*)d_in[3];
    float* out = (float*)d_out;

    cudaFuncSetAttribute(k1_gemm,  cudaFuncAttributeMaxDynamicSharedMemorySize, SMEM_BYTES);
    cudaFuncSetAttribute(k3b_gemm, cudaFuncAttributeMaxDynamicSharedMemorySize, SMEM_BYTES);

    k_cvt_all<<<4096, 256>>>((const float4*)x, (const float4*)Wg,
                             (const float4*)Wu, (const float4*)Wo);
    k1_gemm<<<dim3(2 * SDn / BN, Mn / BM), THR, SMEM_BYTES>>>();
    k3a_scan<<<dim3(2, Mn / TS), 128>>>();
    k_rms<<<Mn / 8, 256>>>();
    k3b_gemm<<<dim3(Dn / BN, Mn / BM), THR, SMEM_BYTES>>>(out);
}

// round 15
// speedup vs baseline: 1.0174x; 1.0051x over previous
#include <cuda_runtime.h>
#include <cuda_fp16.h>
#include <cstdint>
#include <math.h>

// ---------------- problem constants ----------------
#define Bn  4
#define Sn  8192
#define Dn  1024
#define SDn 512
#define Mn  (Bn * Sn)          // 32768 rows
#define TS  128                // scan tile (rows) == BM
#define NT  (Sn / TS)          // 64 tiles per batch
#define RMS_EPS 1.1920929e-07f

// ---------------- GEMM tiling (fp16 operands) ----------------
#define BM 128
#define BN 128
#define THR 128                              // 4 warps: grid 2(M) x 2(N), tile 64x64
#define BKH 64                               // K halves per stage (128 B rows)
#define STAGES 3
#define SROWH 72                             // padded halves per row (64+8) -> 144 B
#define ROWB (SROWH * 2)                     // 144 bytes
#define STAGE_BYTES ((BM + BN) * ROWB)       // 36864 B
#define SMEM_BYTES  (STAGES * STAGE_BYTES)   // 110592 B (2 CTAs/SM)

// ---------------- scratch ----------------
__device__ __align__(128) __half g_xh[Mn * Dn];       // x, fp16
__device__ __align__(128) __half g_wb[2 * SDn * Dn];  // interleaved Wg/Wu rows, fp16
__device__ __align__(128) __half g_wo[Dn * SDn];      // W_out fp16
__device__ __align__(128) __half g_zh[Mn * SDn];      // z then h (fp16, in place)
__device__ __align__(128) float  g_tilesum[(Mn / TS) * SDn];
__device__ __align__(128) float  g_rmsinv[Mn];

// ---------------- helpers ----------------
__device__ __forceinline__ uint32_t smem_u32(const void* p) {
    uint32_t a;
    asm("{ .reg .u64 t; cvta.to.shared.u64 t, %1; cvt.u32.u64 %0, t; }" : "=r"(a) : "l"(p));
    return a;
}
__device__ __forceinline__ void cp16(uint32_t d, const void* s) {
    asm volatile("cp.async.cg.shared.global [%0], [%1], 16;" :: "r"(d), "l"(s));
}
#define CP_COMMIT() asm volatile("cp.async.commit_group;" ::: "memory")
#define CP_WAIT(n)  asm volatile("cp.async.wait_group %0;" :: "n"(n) : "memory")

__device__ __forceinline__ void mma_f16(float* c, const uint32_t* a, uint32_t b0, uint32_t b1) {
    asm volatile(
        "mma.sync.aligned.m16n8k16.row.col.f32.f16.f16.f32 "
        "{%0,%1,%2,%3}, {%4,%5,%6,%7}, {%8,%9}, {%0,%1,%2,%3};"
        : "+f"(c[0]), "+f"(c[1]), "+f"(c[2]), "+f"(c[3])
        : "r"(a[0]), "r"(a[1]), "r"(a[2]), "r"(a[3]), "r"(b0), "r"(b1));
}
__device__ __forceinline__ void ldsm4(uint32_t& r0, uint32_t& r1, uint32_t& r2, uint32_t& r3,
                                      uint32_t addr) {
    asm volatile("ldmatrix.sync.aligned.m8n8.x4.shared.b16 {%0,%1,%2,%3}, [%4];"
        : "=r"(r0), "=r"(r1), "=r"(r2), "=r"(r3) : "r"(addr));
}
__device__ __forceinline__ float sigmoidf_fast(float g) {
    return 1.0f / (1.0f + __expf(-g));
}

// ===========================================================================
// k_cvt_all: one launch converts x, Wg/Wu (interleaved), Wo to fp16
// ===========================================================================
__global__ void k_cvt_all(const float4* __restrict__ x,
                          const float4* __restrict__ wg,
                          const float4* __restrict__ wu,
                          const float4* __restrict__ wo) {
    const int NX = Mn * Dn / 4;      // x float4 count
    const int NW = SDn * Dn / 4;     // per weight matrix
    const int RW = Dn / 4;
    __half2* xd = (__half2*)g_xh;
    __half2* wbd = (__half2*)g_wb;
    __half2* wod = (__half2*)g_wo;
    const int total = NX + 2 * NW;
    for (int i = blockIdx.x * blockDim.x + threadIdx.x; i < total; i += gridDim.x * blockDim.x) {
        if (i < NX) {
            float4 v = x[i];
            xd[2 * i]     = __floats2half2_rn(v.x, v.y);
            xd[2 * i + 1] = __floats2half2_rn(v.z, v.w);
        } else if (i < NX + NW) {
            const int j = i - NX;
            const int r = j / RW, c = j % RW;
            float4 vg = wg[j];
            float4 vu = wu[j];
            size_t dg = (size_t)(2 * r) * (Dn / 2) + 2 * c;
            size_t du = (size_t)(2 * r + 1) * (Dn / 2) + 2 * c;
            wbd[dg]     = __floats2half2_rn(vg.x, vg.y);
            wbd[dg + 1] = __floats2half2_rn(vg.z, vg.w);
            wbd[du]     = __floats2half2_rn(vu.x, vu.y);
            wbd[du + 1] = __floats2half2_rn(vu.z, vu.w);
        } else {
            const int j = i - NX - NW;
            float4 v = wo[j];
            wod[2 * j]     = __floats2half2_rn(v.x, v.y);
            wod[2 * j + 1] = __floats2half2_rn(v.z, v.w);
        }
    }
}

// ===========================================================================
// fp16 GEMM mainloop. CTA tile 128x128, 128 threads, warp tile 64x64.
// 2 CTAs/SM.
// ===========================================================================
struct Frag { float acc[4][8][4]; };

template<int KTOT>
__device__ __forceinline__ void gemm_mainloop(const __half* __restrict__ A,
                                              const __half* __restrict__ B,
                                              int m0, int n0, char* smem, Frag& f) {
    const int t = threadIdx.x;
    const uint32_t sb0 = smem_u32(smem);
    const int lrow = t >> 3;          // 0..15
    const int lseg = t & 7;

    const int iters = KTOT / BKH;

    #pragma unroll
    for (int i = 0; i < 4; i++)
        #pragma unroll
        for (int j = 0; j < 8; j++)
            #pragma unroll
            for (int q = 0; q < 4; q++) f.acc[i][j][q] = 0.f;

    #pragma unroll
    for (int p = 0; p < STAGES - 1; p++) {
        const int k0 = p * BKH;
        #pragma unroll
        for (int i = 0; i < 16; i++) {
            if (i < 8) {
                const int row = 16 * i + lrow;
                cp16(sb0 + p * STAGE_BYTES + row * ROWB + lseg * 16,
                     A + (size_t)(m0 + row) * KTOT + k0 + lseg * 8);
            } else {
                const int row = 16 * (i - 8) + lrow;
                cp16(sb0 + p * STAGE_BYTES + (BM + row) * ROWB + lseg * 16,
                     B + (size_t)(n0 + row) * KTOT + k0 + lseg * 8);
            }
        }
        CP_COMMIT();
    }

    const int wid = t >> 5, lane = t & 31;
    const int wm = wid & 1, wn = wid >> 1;
    const int mrow = wm * 64, nb = wn * 64;

    const uint32_t arow = ((lane >> 3) & 1) * 8 + (lane & 7);
    const uint32_t acolb = ((lane >> 4) & 1) * 16;
    const uint32_t a_off = (mrow + arow) * ROWB + acolb;
    const uint32_t brow = ((lane >> 4) & 1) * 8 + (lane & 7);
    const uint32_t bcolb = ((lane >> 3) & 1) * 16;
    const uint32_t b_off = (BM + nb + brow) * ROWB + bcolb;

    int rs = 0;
    for (int it = 0; it < iters; it++) {
        CP_WAIT(STAGES - 2);
        __syncthreads();

        if (it + STAGES - 1 < iters) {
            int ws = rs + STAGES - 1; if (ws >= STAGES) ws -= STAGES;
            const int k0 = (it + STAGES - 1) * BKH;
            #pragma unroll
            for (int i = 0; i < 16; i++) {
                if (i < 8) {
                    const int row = 16 * i + lrow;
                    cp16(sb0 + ws * STAGE_BYTES + row * ROWB + lseg * 16,
                         A + (size_t)(m0 + row) * KTOT + k0 + lseg * 8);
                } else {
                    const int row = 16 * (i - 8) + lrow;
                    cp16(sb0 + ws * STAGE_BYTES + (BM + row) * ROWB + lseg * 16,
                         B + (size_t)(n0 + row) * KTOT + k0 + lseg * 8);
                }
            }
        }
        CP_COMMIT();

        const uint32_t sbase = sb0 + rs * STAGE_BYTES;

        #pragma unroll
        for (int s = 0; s < BKH / 16; s++) {
            const uint32_t ko = s * 32;
            uint32_t a[4][4];
            #pragma unroll
            for (int mt = 0; mt < 4; mt++)
                ldsm4(a[mt][0], a[mt][1], a[mt][2], a[mt][3],
                      sbase + a_off + mt * 16 * ROWB + ko);
            uint32_t b[8][2];
            #pragma unroll
            for (int p = 0; p < 4; p++)
                ldsm4(b[2*p][0], b[2*p][1], b[2*p+1][0], b[2*p+1][1],
                      sbase + b_off + p * 16 * ROWB + ko);
            #pragma unroll
            for (int nt = 0; nt < 8; nt++)
                #pragma unroll
                for (int mt = 0; mt < 4; mt++)
                    mma_f16(f.acc[mt][nt], a[mt], b[nt][0], b[nt][1]);
        }
        rs++; if (rs == STAGES) rs = 0;
    }
    __syncthreads();
}

// ===========================================================================
// k1: C = x @ Wb^T. Epilogue: z = sigmoid(g)*u -> fp16 g_zh + tile col sums.
// ===========================================================================
__global__ void __launch_bounds__(THR, 2) k1_gemm() {
    extern __shared__ char smem[];
    const int n0 = blockIdx.x * BN;
    const int m0 = blockIdx.y * BM;
    Frag f;
    gemm_mainloop<Dn>(g_xh, g_wb, m0, n0, smem, f);

    const int t = threadIdx.x;
    const int wid = t >> 5, lane = t & 31;
    const int wm = wid & 1, wn = wid >> 1;
    const int gr = lane >> 2, gc = lane & 3;
    const int zbase = n0 >> 1;             // 64 z-cols per CTA

    float* csum = (float*)smem;
    if (t < 64) csum[t] = 0.f;
    __syncthreads();

    #pragma unroll
    for (int nt = 0; nt < 8; nt++) {
        float cs = 0.f;
        #pragma unroll
        for (int mt = 0; mt < 4; mt++) {
            const int r0 = m0 + wm * 64 + mt * 16 + gr;
            const int zc = zbase + wn * 32 + nt * 4 + gc;
            __half h0 = __float2half_rn(f.acc[mt][nt][1] * sigmoidf_fast(f.acc[mt][nt][0]));
            __half h1 = __float2half_rn(f.acc[mt][nt][3] * sigmoidf_fast(f.acc[mt][nt][2]));
            g_zh[(size_t)r0 * SDn + zc] = h0;
            g_zh[(size_t)(r0 + 8) * SDn + zc] = h1;
            cs += __half2float(h0) + __half2float(h1);
        }
        cs += __shfl_xor_sync(0xffffffffu, cs, 4);
        cs += __shfl_xor_sync(0xffffffffu, cs, 8);
        cs += __shfl_xor_sync(0xffffffffu, cs, 16);
        if (gr == 0)
            atomicAdd(&csum[wn * 32 + nt * 4 + gc], cs);
    }
    __syncthreads();
    if (t < 64)
        g_tilesum[(size_t)blockIdx.y * SDn + zbase + t] = csum[t];
}

// ===========================================================================
// k3a: scan + fused RMS. One 256-thread block per tile (all 256 half2 cols).
// Inline exclusive tile-prefix; at each row step, warp-reduce sum-of-squares
// of the freshly rounded h values into ssp[r][warp]; fold at the end.
// ===========================================================================
__global__ void __launch_bounds__(256) k3a_scan() {
    const int mt = blockIdx.x;                         // global tile 0..255
    const int ty = mt & (NT - 1);                      // tile within batch
    const int b = mt >> 6;                             // batch
    const int k2i = threadIdx.x;                       // half2 column (0..255)
    const int warp = threadIdx.x >> 5, lane = threadIdx.x & 31;
    const int base = mt * TS;

    __shared__ float ssp[TS][8];

    // exclusive prefix of tile sums for this channel pair
    float c0 = 0.f, c1 = 0.f;
    for (int i = 0; i < ty; i++) {
        const float2 v = *(const float2*)&g_tilesum[(size_t)(b * NT + i) * SDn + 2 * k2i];
        c0 += v.x; c1 += v.y;
    }

    __half2* zp = (__half2*)g_zh + ((size_t)base * SDn >> 1) + k2i;

    #pragma unroll 4
    for (int r = 0; r < TS; r++) {
        float2 zv = __half22float2(zp[0]);
        c0 += zv.x;
        c1 += zv.y;
        const float inv = __frcp_rn((float)(ty * TS + r + 1));
        __half2 hh = __floats2half2_rn(c0 * inv, c1 * inv);
        zp[0] = hh;
        float2 hr = __half22float2(hh);
        float sq = hr.x * hr.x + hr.y * hr.y;
        #pragma unroll
        for (int o = 16; o > 0; o >>= 1) sq += __shfl_xor_sync(0xffffffffu, sq, o);
        if (lane == 0) ssp[r][warp] = sq;
        zp += SDn / 2;
    }
    __syncthreads();
    if (threadIdx.x < TS) {
        float s = 0.f;
        #pragma unroll
        for (int w = 0; w < 8; w++) s += ssp[threadIdx.x][w];
        g_rmsinv[base + threadIdx.x] = rsqrtf(s * (1.0f / SDn) + RMS_EPS);
    }
}

// ===========================================================================
// k3b: out = rms_inv[m] * (h @ Wo^T), M=32768, N=1024, K=512 (fp16 inputs)
// ===========================================================================
__global__ void __launch_bounds__(THR, 2) k3b_gemm(float* __restrict__ out) {
    extern __shared__ char smem[];
    const int n0 = blockIdx.x * BN;
    const int m0 = blockIdx.y * BM;
    Frag f;
    gemm_mainloop<SDn>(g_zh, g_wo, m0, n0, smem, f);

    const int t = threadIdx.x;
    const int wid = t >> 5, lane = t & 31;
    const int wm = wid & 1, wn = wid >> 1;
    const int gr = lane >> 2, gc = lane & 3;

    #pragma unroll
    for (int mt = 0; mt < 4; mt++) {
        const int r0 = m0 + wm * 64 + mt * 16 + gr;
        const float ri0 = g_rmsinv[r0];
        const float ri1 = g_rmsinv[r0 + 8];
        #pragma unroll
        for (int nt = 0; nt < 8; nt++) {
            const int col = n0 + wn * 64 + nt * 8 + gc * 2;
            float2 v0 = { f.acc[mt][nt][0] * ri0, f.acc[mt][nt][1] * ri0 };
            float2 v1 = { f.acc[mt][nt][2] * ri1, f.acc[mt][nt][3] * ri1 };
            *(float2*)&out[(size_t)r0 * Dn + col] = v0;
            *(float2*)&out[(size_t)(r0 + 8) * Dn + col] = v1;
        }
    }
}

// ===========================================================================
// host side — single stream, no runtime allocation of any kind
// ===========================================================================
extern "C" void kernel_launch(void* const* d_in, const int* in_sizes, int n_in,
                              void* d_out, int out_size) {
    const float* x  = (const float*)d_in[0];
    const float* Wu = (const float*)d_in[1];
    const float* Wg = (const float*)d_in[2];
    const float* Wo = (const float*)d_in[3];
    float* out = (float*)d_out;

    cudaFuncSetAttribute(k1_gemm,  cudaFuncAttributeMaxDynamicSharedMemorySize, SMEM_BYTES);
    cudaFuncSetAttribute(k3b_gemm, cudaFuncAttributeMaxDynamicSharedMemorySize, SMEM_BYTES);

    k_cvt_all<<<4096, 256>>>((const float4*)x, (const float4*)Wg,
                             (const float4*)Wu, (const float4*)Wo);
    k1_gemm<<<dim3(2 * SDn / BN, Mn / BM), THR, SMEM_BYTES>>>();
    k3a_scan<<<Mn / TS, 256>>>();
    k3b_gemm<<<dim3(Dn / BN, Mn / BM), THR, SMEM_BYTES>>>(out);
}

// round 16
// speedup vs baseline: 1.0190x; 1.0016x over previous
#include <cuda_runtime.h>
#include <cuda_fp16.h>
#include <cstdint>
#include <math.h>

// ---------------- problem constants ----------------
#define Bn  4
#define Sn  8192
#define Dn  1024
#define SDn 512
#define Mn  (Bn * Sn)          // 32768 rows
#define TS  128                // scan tile (rows) == BM
#define NT  (Sn / TS)          // 64 tiles per batch
#define RMS_EPS 1.1920929e-07f

// ---------------- GEMM tiling (fp16 operands) ----------------
#define BM 128
#define BN 128
#define THR 128                              // 4 warps: grid 2(M) x 2(N), tile 64x64
#define BKH 64                               // K halves per stage (128 B rows)
#define STAGES 3
#define SROWH 72                             // padded halves per row (64+8) -> 144 B
#define ROWB (SROWH * 2)                     // 144 bytes
#define STAGE_BYTES ((BM + BN) * ROWB)       // 36864 B
#define SMEM_BYTES  (STAGES * STAGE_BYTES)   // 110592 B (2 CTAs/SM)

// ---------------- scratch ----------------
__device__ __align__(128) __half g_xh[Mn * Dn];       // x, fp16
__device__ __align__(128) __half g_wb[2 * SDn * Dn];  // interleaved Wg/Wu rows, fp16
__device__ __align__(128) __half g_wo[Dn * SDn];      // W_out fp16
__device__ __align__(128) __half g_zh[Mn * SDn];      // z then h (fp16, in place)
__device__ __align__(128) float  g_tilesum[(Mn / TS) * SDn];
__device__ __align__(128) float  g_rmsinv[Mn];

// ---------------- helpers ----------------
__device__ __forceinline__ uint32_t smem_u32(const void* p) {
    uint32_t a;
    asm("{ .reg .u64 t; cvta.to.shared.u64 t, %1; cvt.u32.u64 %0, t; }" : "=r"(a) : "l"(p));
    return a;
}
__device__ __forceinline__ void cp16(uint32_t d, const void* s) {
    asm volatile("cp.async.cg.shared.global [%0], [%1], 16;" :: "r"(d), "l"(s));
}
#define CP_COMMIT() asm volatile("cp.async.commit_group;" ::: "memory")
#define CP_WAIT(n)  asm volatile("cp.async.wait_group %0;" :: "n"(n) : "memory")

__device__ __forceinline__ void mma_f16(float* c, const uint32_t* a, uint32_t b0, uint32_t b1) {
    asm volatile(
        "mma.sync.aligned.m16n8k16.row.col.f32.f16.f16.f32 "
        "{%0,%1,%2,%3}, {%4,%5,%6,%7}, {%8,%9}, {%0,%1,%2,%3};"
        : "+f"(c[0]), "+f"(c[1]), "+f"(c[2]), "+f"(c[3])
        : "r"(a[0]), "r"(a[1]), "r"(a[2]), "r"(a[3]), "r"(b0), "r"(b1));
}
__device__ __forceinline__ void ldsm4(uint32_t& r0, uint32_t& r1, uint32_t& r2, uint32_t& r3,
                                      uint32_t addr) {
    asm volatile("ldmatrix.sync.aligned.m8n8.x4.shared.b16 {%0,%1,%2,%3}, [%4];"
        : "=r"(r0), "=r"(r1), "=r"(r2), "=r"(r3) : "r"(addr));
}
__device__ __forceinline__ float sigmoidf_fast(float g) {
    return 1.0f / (1.0f + __expf(-g));
}
__device__ __forceinline__ void grid_dep_sync() {
    asm volatile("griddepcontrol.wait;" ::: "memory");
}
__device__ __forceinline__ void grid_dep_trigger() {
    asm volatile("griddepcontrol.launch_dependents;" ::: "memory");
}

// ===========================================================================
// k_cvt_all: one launch converts x, Wg/Wu (interleaved), Wo to fp16
// ===========================================================================
__global__ void k_cvt_all(const float4* __restrict__ x,
                          const float4* __restrict__ wg,
                          const float4* __restrict__ wu,
                          const float4* __restrict__ wo) {
    const int NX = Mn * Dn / 4;      // x float4 count
    const int NW = SDn * Dn / 4;     // per weight matrix
    const int RW = Dn / 4;
    __half2* xd = (__half2*)g_xh;
    __half2* wbd = (__half2*)g_wb;
    __half2* wod = (__half2*)g_wo;
    const int total = NX + 2 * NW;
    for (int i = blockIdx.x * blockDim.x + threadIdx.x; i < total; i += gridDim.x * blockDim.x) {
        if (i < NX) {
            float4 v = x[i];
            xd[2 * i]     = __floats2half2_rn(v.x, v.y);
            xd[2 * i + 1] = __floats2half2_rn(v.z, v.w);
        } else if (i < NX + NW) {
            const int j = i - NX;
            const int r = j / RW, c = j % RW;
            float4 vg = wg[j];
            float4 vu = wu[j];
            size_t dg = (size_t)(2 * r) * (Dn / 2) + 2 * c;
            size_t du = (size_t)(2 * r + 1) * (Dn / 2) + 2 * c;
            wbd[dg]     = __floats2half2_rn(vg.x, vg.y);
            wbd[dg + 1] = __floats2half2_rn(vg.z, vg.w);
            wbd[du]     = __floats2half2_rn(vu.x, vu.y);
            wbd[du + 1] = __floats2half2_rn(vu.z, vu.w);
        } else {
            const int j = i - NX - NW;
            float4 v = wo[j];
            wod[2 * j]     = __floats2half2_rn(v.x, v.y);
            wod[2 * j + 1] = __floats2half2_rn(v.z, v.w);
        }
    }
    grid_dep_trigger();
}

// ===========================================================================
// fp16 GEMM mainloop. CTA tile 128x128, 128 threads, warp tile 64x64.
// 2 CTAs/SM. grid_dep_sync() before first upstream read.
// ===========================================================================
struct Frag { float acc[4][8][4]; };

template<int KTOT>
__device__ __forceinline__ void gemm_mainloop(const __half* __restrict__ A,
                                              const __half* __restrict__ B,
                                              int m0, int n0, char* smem, Frag& f) {
    const int t = threadIdx.x;
    const uint32_t sb0 = smem_u32(smem);
    const int lrow = t >> 3;          // 0..15
    const int lseg = t & 7;

    const int iters = KTOT / BKH;

    #pragma unroll
    for (int i = 0; i < 4; i++)
        #pragma unroll
        for (int j = 0; j < 8; j++)
            #pragma unroll
            for (int q = 0; q < 4; q++) f.acc[i][j][q] = 0.f;

    grid_dep_sync();   // upstream grid's writes now visible

    #pragma unroll
    for (int p = 0; p < STAGES - 1; p++) {
        const int k0 = p * BKH;
        #pragma unroll
        for (int i = 0; i < 16; i++) {
            if (i < 8) {
                const int row = 16 * i + lrow;
                cp16(sb0 + p * STAGE_BYTES + row * ROWB + lseg * 16,
                     A + (size_t)(m0 + row) * KTOT + k0 + lseg * 8);
            } else {
                const int row = 16 * (i - 8) + lrow;
                cp16(sb0 + p * STAGE_BYTES + (BM + row) * ROWB + lseg * 16,
                     B + (size_t)(n0 + row) * KTOT + k0 + lseg * 8);
            }
        }
        CP_COMMIT();
    }

    const int wid = t >> 5, lane = t & 31;
    const int wm = wid & 1, wn = wid >> 1;
    const int mrow = wm * 64, nb = wn * 64;

    const uint32_t arow = ((lane >> 3) & 1) * 8 + (lane & 7);
    const uint32_t acolb = ((lane >> 4) & 1) * 16;
    const uint32_t a_off = (mrow + arow) * ROWB + acolb;
    const uint32_t brow = ((lane >> 4) & 1) * 8 + (lane & 7);
    const uint32_t bcolb = ((lane >> 3) & 1) * 16;
    const uint32_t b_off = (BM + nb + brow) * ROWB + bcolb;

    int rs = 0;
    for (int it = 0; it < iters; it++) {
        CP_WAIT(STAGES - 2);
        __syncthreads();

        if (it + STAGES - 1 < iters) {
            int ws = rs + STAGES - 1; if (ws >= STAGES) ws -= STAGES;
            const int k0 = (it + STAGES - 1) * BKH;
            #pragma unroll
            for (int i = 0; i < 16; i++) {
                if (i < 8) {
                    const int row = 16 * i + lrow;
                    cp16(sb0 + ws * STAGE_BYTES + row * ROWB + lseg * 16,
                         A + (size_t)(m0 + row) * KTOT + k0 + lseg * 8);
                } else {
                    const int row = 16 * (i - 8) + lrow;
                    cp16(sb0 + ws * STAGE_BYTES + (BM + row) * ROWB + lseg * 16,
                         B + (size_t)(n0 + row) * KTOT + k0 + lseg * 8);
                }
            }
        }
        CP_COMMIT();

        const uint32_t sbase = sb0 + rs * STAGE_BYTES;

        #pragma unroll
        for (int s = 0; s < BKH / 16; s++) {
            const uint32_t ko = s * 32;
            uint32_t a[4][4];
            #pragma unroll
            for (int mt = 0; mt < 4; mt++)
                ldsm4(a[mt][0], a[mt][1], a[mt][2], a[mt][3],
                      sbase + a_off + mt * 16 * ROWB + ko);
            uint32_t b[8][2];
            #pragma unroll
            for (int p = 0; p < 4; p++)
                ldsm4(b[2*p][0], b[2*p][1], b[2*p+1][0], b[2*p+1][1],
                      sbase + b_off + p * 16 * ROWB + ko);
            #pragma unroll
            for (int nt = 0; nt < 8; nt++)
                #pragma unroll
                for (int mt = 0; mt < 4; mt++)
                    mma_f16(f.acc[mt][nt], a[mt], b[nt][0], b[nt][1]);
        }
        rs++; if (rs == STAGES) rs = 0;
    }
    __syncthreads();
}

// ===========================================================================
// k1: C = x @ Wb^T. Epilogue: z = sigmoid(g)*u -> fp16 g_zh + tile col sums.
// ===========================================================================
__global__ void __launch_bounds__(THR, 2) k1_gemm() {
    extern __shared__ char smem[];
    const int n0 = blockIdx.x * BN;
    const int m0 = blockIdx.y * BM;
    Frag f;
    gemm_mainloop<Dn>(g_xh, g_wb, m0, n0, smem, f);

    const int t = threadIdx.x;
    const int wid = t >> 5, lane = t & 31;
    const int wm = wid & 1, wn = wid >> 1;
    const int gr = lane >> 2, gc = lane & 3;
    const int zbase = n0 >> 1;             // 64 z-cols per CTA

    float* csum = (float*)smem;
    if (t < 64) csum[t] = 0.f;
    __syncthreads();

    #pragma unroll
    for (int nt = 0; nt < 8; nt++) {
        float cs = 0.f;
        #pragma unroll
        for (int mt = 0; mt < 4; mt++) {
            const int r0 = m0 + wm * 64 + mt * 16 + gr;
            const int zc = zbase + wn * 32 + nt * 4 + gc;
            __half h0 = __float2half_rn(f.acc[mt][nt][1] * sigmoidf_fast(f.acc[mt][nt][0]));
            __half h1 = __float2half_rn(f.acc[mt][nt][3] * sigmoidf_fast(f.acc[mt][nt][2]));
            g_zh[(size_t)r0 * SDn + zc] = h0;
            g_zh[(size_t)(r0 + 8) * SDn + zc] = h1;
            cs += __half2float(h0) + __half2float(h1);
        }
        cs += __shfl_xor_sync(0xffffffffu, cs, 4);
        cs += __shfl_xor_sync(0xffffffffu, cs, 8);
        cs += __shfl_xor_sync(0xffffffffu, cs, 16);
        if (gr == 0)
            atomicAdd(&csum[wn * 32 + nt * 4 + gc], cs);
    }
    __syncthreads();
    if (t < 64)
        g_tilesum[(size_t)blockIdx.y * SDn + zbase + t] = csum[t];
    grid_dep_trigger();
}

// ===========================================================================
// k3a: scan + fused RMS. One 256-thread block per tile (all 256 half2 cols).
// ===========================================================================
__global__ void __launch_bounds__(256) k3a_scan() {
    const int mt = blockIdx.x;                         // global tile 0..255
    const int ty = mt & (NT - 1);                      // tile within batch
    const int b = mt >> 6;                             // batch
    const int k2i = threadIdx.x;                       // half2 column (0..255)
    const int warp = threadIdx.x >> 5, lane = threadIdx.x & 31;
    const int base = mt * TS;

    __shared__ float ssp[TS][8];

    grid_dep_sync();

    // exclusive prefix of tile sums for this channel pair
    float c0 = 0.f, c1 = 0.f;
    for (int i = 0; i < ty; i++) {
        const float2 v = *(const float2*)&g_tilesum[(size_t)(b * NT + i) * SDn + 2 * k2i];
        c0 += v.x; c1 += v.y;
    }

    __half2* zp = (__half2*)g_zh + ((size_t)base * SDn >> 1) + k2i;

    #pragma unroll 4
    for (int r = 0; r < TS; r++) {
        float2 zv = __half22float2(zp[0]);
        c0 += zv.x;
        c1 += zv.y;
        const float inv = __frcp_rn((float)(ty * TS + r + 1));
        __half2 hh = __floats2half2_rn(c0 * inv, c1 * inv);
        zp[0] = hh;
        float2 hr = __half22float2(hh);
        float sq = hr.x * hr.x + hr.y * hr.y;
        #pragma unroll
        for (int o = 16; o > 0; o >>= 1) sq += __shfl_xor_sync(0xffffffffu, sq, o);
        if (lane == 0) ssp[r][warp] = sq;
        zp += SDn / 2;
    }
    __syncthreads();
    if (threadIdx.x < TS) {
        float s = 0.f;
        #pragma unroll
        for (int w = 0; w < 8; w++) s += ssp[threadIdx.x][w];
        g_rmsinv[base + threadIdx.x] = rsqrtf(s * (1.0f / SDn) + RMS_EPS);
    }
    grid_dep_trigger();
}

// ===========================================================================
// k3b: out = rms_inv[m] * (h @ Wo^T), M=32768, N=1024, K=512 (fp16 inputs)
// ===========================================================================
__global__ void __launch_bounds__(THR, 2) k3b_gemm(float* __restrict__ out) {
    extern __shared__ char smem[];
    const int n0 = blockIdx.x * BN;
    const int m0 = blockIdx.y * BM;
    Frag f;
    gemm_mainloop<SDn>(g_zh, g_wo, m0, n0, smem, f);

    const int t = threadIdx.x;
    const int wid = t >> 5, lane = t & 31;
    const int wm = wid & 1, wn = wid >> 1;
    const int gr = lane >> 2, gc = lane & 3;

    #pragma unroll
    for (int mt = 0; mt < 4; mt++) {
        const int r0 = m0 + wm * 64 + mt * 16 + gr;
        const float ri0 = g_rmsinv[r0];
        const float ri1 = g_rmsinv[r0 + 8];
        #pragma unroll
        for (int nt = 0; nt < 8; nt++) {
            const int col = n0 + wn * 64 + nt * 8 + gc * 2;
            float2 v0 = { f.acc[mt][nt][0] * ri0, f.acc[mt][nt][1] * ri0 };
            float2 v1 = { f.acc[mt][nt][2] * ri1, f.acc[mt][nt][3] * ri1 };
            *(float2*)&out[(size_t)r0 * Dn + col] = v0;
            *(float2*)&out[(size_t)(r0 + 8) * Dn + col] = v1;
        }
    }
}

// ===========================================================================
// host side — single stream; PDL on dependent launches (no allocation)
// ===========================================================================
template <typename... Args>
static void launch_pdl(void (*kern)(Args...), dim3 grid, dim3 block,
                       size_t smem, Args... args) {
    cudaLaunchAttribute attrs[1];
    attrs[0].id = cudaLaunchAttributeProgrammaticStreamSerialization;
    attrs[0].val.programmaticStreamSerializationAllowed = 1;
    cudaLaunchConfig_t cfg{};
    cfg.gridDim = grid;
    cfg.blockDim = block;
    cfg.dynamicSmemBytes = smem;
    cfg.stream = 0;
    cfg.attrs = attrs;
    cfg.numAttrs = 1;
    cudaLaunchKernelEx(&cfg, kern, args...);
}

extern "C" void kernel_launch(void* const* d_in, const int* in_sizes, int n_in,
                              void* d_out, int out_size) {
    const float* x  = (const float*)d_in[0];
    const float* Wu = (const float*)d_in[1];
    const float* Wg = (const float*)d_in[2];
    const float* Wo = (const float*)d_in[3];
    float* out = (float*)d_out;

    cudaFuncSetAttribute(k1_gemm,  cudaFuncAttributeMaxDynamicSharedMemorySize, SMEM_BYTES);
    cudaFuncSetAttribute(k3b_gemm, cudaFuncAttributeMaxDynamicSharedMemorySize, SMEM_BYTES);

    k_cvt_all<<<4096, 256>>>((const float4*)x, (const float4*)Wg,
                             (const float4*)Wu, (const float4*)Wo);
    launch_pdl(k1_gemm, dim3(2 * SDn / BN, Mn / BM), dim3(THR), (size_t)SMEM_BYTES);
    launch_pdl(k3a_scan, dim3(Mn / TS), dim3(256), (size_t)0);
    launch_pdl(k3b_gemm, dim3(Dn / BN, Mn / BM), dim3(THR), (size_t)SMEM_BYTES,
               (float*)out);
}

// round 17
// speedup vs baseline: 1.1193x; 1.0985x over previous
#include <cuda_runtime.h>
#include <cuda_fp16.h>
#include <cstdint>
#include <math.h>

// ---------------- problem constants ----------------
#define Bn  4
#define Sn  8192
#define Dn  1024
#define SDn 512
#define Mn  (Bn * Sn)          // 32768 rows
#define TS  128                // scan tile (rows) == BM
#define NT  (Sn / TS)          // 64 tiles per batch
#define RMS_EPS 1.1920929e-07f

// ---------------- GEMM tiling (fp16 operands) ----------------
#define BM 128
#define BN 128
#define THR 128                              // 4 warps: grid 2(M) x 2(N), tile 64x64
#define BKH 64                               // K halves per stage (128 B rows)
#define STAGES 3
#define SROWH 72                             // padded halves per row (64+8) -> 144 B
#define ROWB (SROWH * 2)                     // 144 bytes
#define STAGE_BYTES ((BM + BN) * ROWB)       // 36864 B
#define SMEM_BYTES  (STAGES * STAGE_BYTES)   // 110592 B (2 CTAs/SM)

// ---------------- scratch ----------------
__device__ __align__(128) __half g_xh[Mn * Dn];       // x, fp16
__device__ __align__(128) __half g_wb[2 * SDn * Dn];  // interleaved Wg/Wu rows, fp16
__device__ __align__(128) __half g_wo[Dn * SDn];      // W_out fp16
__device__ __align__(128) __half g_zh[Mn * SDn];      // z then h (fp16, in place)
__device__ __align__(128) float  g_tilesum[(Mn / TS) * SDn];
__device__ __align__(128) float  g_rmsinv[Mn];

// ---------------- helpers ----------------
__device__ __forceinline__ uint32_t smem_u32(const void* p) {
    uint32_t a;
    asm("{ .reg .u64 t; cvta.to.shared.u64 t, %1; cvt.u32.u64 %0, t; }" : "=r"(a) : "l"(p));
    return a;
}
__device__ __forceinline__ void cp16(uint32_t d, const void* s) {
    asm volatile("cp.async.cg.shared.global [%0], [%1], 16;" :: "r"(d), "l"(s));
}
#define CP_COMMIT() asm volatile("cp.async.commit_group;" ::: "memory")
#define CP_WAIT(n)  asm volatile("cp.async.wait_group %0;" :: "n"(n) : "memory")

__device__ __forceinline__ void mma_f16(float* c, const uint32_t* a, uint32_t b0, uint32_t b1) {
    asm volatile(
        "mma.sync.aligned.m16n8k16.row.col.f32.f16.f16.f32 "
        "{%0,%1,%2,%3}, {%4,%5,%6,%7}, {%8,%9}, {%0,%1,%2,%3};"
        : "+f"(c[0]), "+f"(c[1]), "+f"(c[2]), "+f"(c[3])
        : "r"(a[0]), "r"(a[1]), "r"(a[2]), "r"(a[3]), "r"(b0), "r"(b1));
}
__device__ __forceinline__ void ldsm4(uint32_t& r0, uint32_t& r1, uint32_t& r2, uint32_t& r3,
                                      uint32_t addr) {
    asm volatile("ldmatrix.sync.aligned.m8n8.x4.shared.b16 {%0,%1,%2,%3}, [%4];"
        : "=r"(r0), "=r"(r1), "=r"(r2), "=r"(r3) : "r"(addr));
}
__device__ __forceinline__ float sigmoidf_fast(float g) {
    return 1.0f / (1.0f + __expf(-g));
}
__device__ __forceinline__ void grid_dep_sync() {
    asm volatile("griddepcontrol.wait;" ::: "memory");
}
__device__ __forceinline__ void grid_dep_trigger() {
    asm volatile("griddepcontrol.launch_dependents;" ::: "memory");
}
__device__ __forceinline__ uint32_t pack_h2(float a, float b) {
    __half2 h = __floats2half2_rn(a, b);
    return *(uint32_t*)&h;
}

// ===========================================================================
// k_cvt_all: one launch converts x (paired float4 -> uint4 stores),
// Wg/Wu (interleaved), Wo to fp16
// ===========================================================================
__global__ void k_cvt_all(const float4* __restrict__ x,
                          const float4* __restrict__ wg,
                          const float4* __restrict__ wu,
                          const float4* __restrict__ wo) {
    const int NX8 = Mn * Dn / 8;     // x: process 8 floats (2 float4) per index
    const int NW = SDn * Dn / 4;     // per weight matrix (float4 units)
    const int RW = Dn / 4;
    uint4* xd = (uint4*)g_xh;
    __half2* wbd = (__half2*)g_wb;
    __half2* wod = (__half2*)g_wo;
    const int total = NX8 + 2 * NW;
    for (int i = blockIdx.x * blockDim.x + threadIdx.x; i < total; i += gridDim.x * blockDim.x) {
        if (i < NX8) {
            float4 v0 = x[2 * i];
            float4 v1 = x[2 * i + 1];
            uint4 o;
            o.x = pack_h2(v0.x, v0.y);
            o.y = pack_h2(v0.z, v0.w);
            o.z = pack_h2(v1.x, v1.y);
            o.w = pack_h2(v1.z, v1.w);
            xd[i] = o;
        } else if (i < NX8 + NW) {
            const int j = i - NX8;
            const int r = j / RW, c = j % RW;
            float4 vg = wg[j];
            float4 vu = wu[j];
            size_t dg = (size_t)(2 * r) * (Dn / 2) + 2 * c;
            size_t du = (size_t)(2 * r + 1) * (Dn / 2) + 2 * c;
            wbd[dg]     = __floats2half2_rn(vg.x, vg.y);
            wbd[dg + 1] = __floats2half2_rn(vg.z, vg.w);
            wbd[du]     = __floats2half2_rn(vu.x, vu.y);
            wbd[du + 1] = __floats2half2_rn(vu.z, vu.w);
        } else {
            const int j = i - NX8 - NW;
            float4 v = wo[j];
            wod[2 * j]     = __floats2half2_rn(v.x, v.y);
            wod[2 * j + 1] = __floats2half2_rn(v.z, v.w);
        }
    }
    grid_dep_trigger();
}

// ===========================================================================
// fp16 GEMM mainloop. CTA tile 128x128, 128 threads, warp tile 64x64.
// 2 CTAs/SM. grid_dep_sync() before first upstream read.
// ===========================================================================
struct Frag { float acc[4][8][4]; };

template<int KTOT>
__device__ __forceinline__ void gemm_mainloop(const __half* __restrict__ A,
                                              const __half* __restrict__ B,
                                              int m0, int n0, char* smem, Frag& f) {
    const int t = threadIdx.x;
    const uint32_t sb0 = smem_u32(smem);
    const int lrow = t >> 3;          // 0..15
    const int lseg = t & 7;

    const int iters = KTOT / BKH;

    #pragma unroll
    for (int i = 0; i < 4; i++)
        #pragma unroll
        for (int j = 0; j < 8; j++)
            #pragma unroll
            for (int q = 0; q < 4; q++) f.acc[i][j][q] = 0.f;

    grid_dep_sync();   // upstream grid's writes now visible

    #pragma unroll
    for (int p = 0; p < STAGES - 1; p++) {
        const int k0 = p * BKH;
        #pragma unroll
        for (int i = 0; i < 16; i++) {
            if (i < 8) {
                const int row = 16 * i + lrow;
                cp16(sb0 + p * STAGE_BYTES + row * ROWB + lseg * 16,
                     A + (size_t)(m0 + row) * KTOT + k0 + lseg * 8);
            } else {
                const int row = 16 * (i - 8) + lrow;
                cp16(sb0 + p * STAGE_BYTES + (BM + row) * ROWB + lseg * 16,
                     B + (size_t)(n0 + row) * KTOT + k0 + lseg * 8);
            }
        }
        CP_COMMIT();
    }

    const int wid = t >> 5, lane = t & 31;
    const int wm = wid & 1, wn = wid >> 1;
    const int mrow = wm * 64, nb = wn * 64;

    const uint32_t arow = ((lane >> 3) & 1) * 8 + (lane & 7);
    const uint32_t acolb = ((lane >> 4) & 1) * 16;
    const uint32_t a_off = (mrow + arow) * ROWB + acolb;
    const uint32_t brow = ((lane >> 4) & 1) * 8 + (lane & 7);
    const uint32_t bcolb = ((lane >> 3) & 1) * 16;
    const uint32_t b_off = (BM + nb + brow) * ROWB + bcolb;

    int rs = 0;
    for (int it = 0; it < iters; it++) {
        CP_WAIT(STAGES - 2);
        __syncthreads();

        if (it + STAGES - 1 < iters) {
            int ws = rs + STAGES - 1; if (ws >= STAGES) ws -= STAGES;
            const int k0 = (it + STAGES - 1) * BKH;
            #pragma unroll
            for (int i = 0; i < 16; i++) {
                if (i < 8) {
                    const int row = 16 * i + lrow;
                    cp16(sb0 + ws * STAGE_BYTES + row * ROWB + lseg * 16,
                         A + (size_t)(m0 + row) * KTOT + k0 + lseg * 8);
                } else {
                    const int row = 16 * (i - 8) + lrow;
                    cp16(sb0 + ws * STAGE_BYTES + (BM + row) * ROWB + lseg * 16,
                         B + (size_t)(n0 + row) * KTOT + k0 + lseg * 8);
                }
            }
        }
        CP_COMMIT();

        const uint32_t sbase = sb0 + rs * STAGE_BYTES;

        #pragma unroll
        for (int s = 0; s < BKH / 16; s++) {
            const uint32_t ko = s * 32;
            uint32_t a[4][4];
            #pragma unroll
            for (int mt = 0; mt < 4; mt++)
                ldsm4(a[mt][0], a[mt][1], a[mt][2], a[mt][3],
                      sbase + a_off + mt * 16 * ROWB + ko);
            uint32_t b[8][2];
            #pragma unroll
            for (int p = 0; p < 4; p++)
                ldsm4(b[2*p][0], b[2*p][1], b[2*p+1][0], b[2*p+1][1],
                      sbase + b_off + p * 16 * ROWB + ko);
            #pragma unroll
            for (int nt = 0; nt < 8; nt++)
                #pragma unroll
                for (int mt = 0; mt < 4; mt++)
                    mma_f16(f.acc[mt][nt], a[mt], b[nt][0], b[nt][1]);
        }
        rs++; if (rs == STAGES) rs = 0;
    }
    __syncthreads();
}

// ===========================================================================
// k1: C = x @ Wb^T. Epilogue: z = sigmoid(g)*u -> fp16 g_zh + tile col sums.
// ===========================================================================
__global__ void __launch_bounds__(THR, 2) k1_gemm() {
    extern __shared__ char smem[];
    const int n0 = blockIdx.x * BN;
    const int m0 = blockIdx.y * BM;
    Frag f;
    gemm_mainloop<Dn>(g_xh, g_wb, m0, n0, smem, f);

    const int t = threadIdx.x;
    const int wid = t >> 5, lane = t & 31;
    const int wm = wid & 1, wn = wid >> 1;
    const int gr = lane >> 2, gc = lane & 3;
    const int zbase = n0 >> 1;             // 64 z-cols per CTA

    float* csum = (float*)smem;
    if (t < 64) csum[t] = 0.f;
    __syncthreads();

    #pragma unroll
    for (int nt = 0; nt < 8; nt++) {
        float cs = 0.f;
        #pragma unroll
        for (int mt = 0; mt < 4; mt++) {
            const int r0 = m0 + wm * 64 + mt * 16 + gr;
            const int zc = zbase + wn * 32 + nt * 4 + gc;
            __half h0 = __float2half_rn(f.acc[mt][nt][1] * sigmoidf_fast(f.acc[mt][nt][0]));
            __half h1 = __float2half_rn(f.acc[mt][nt][3] * sigmoidf_fast(f.acc[mt][nt][2]));
            g_zh[(size_t)r0 * SDn + zc] = h0;
            g_zh[(size_t)(r0 + 8) * SDn + zc] = h1;
            cs += __half2float(h0) + __half2float(h1);
        }
        cs += __shfl_xor_sync(0xffffffffu, cs, 4);
        cs += __shfl_xor_sync(0xffffffffu, cs, 8);
        cs += __shfl_xor_sync(0xffffffffu, cs, 16);
        if (gr == 0)
            atomicAdd(&csum[wn * 32 + nt * 4 + gc], cs);
    }
    __syncthreads();
    if (t < 64)
        g_tilesum[(size_t)blockIdx.y * SDn + zbase + t] = csum[t];
    grid_dep_trigger();
}

// ===========================================================================
// k3a: scan + fused RMS. One 256-thread block per tile (all 256 half2 cols).
// Unroll-8 with hoisted row loads for DRAM MLP.
// ===========================================================================
__global__ void __launch_bounds__(256) k3a_scan() {
    const int mt = blockIdx.x;                         // global tile 0..255
    const int ty = mt & (NT - 1);                      // tile within batch
    const int b = mt >> 6;                             // batch
    const int k2i = threadIdx.x;                       // half2 column (0..255)
    const int warp = threadIdx.x >> 5, lane = threadIdx.x & 31;
    const int base = mt * TS;

    __shared__ float ssp[TS][8];

    grid_dep_sync();

    // exclusive prefix of tile sums for this channel pair
    float c0 = 0.f, c1 = 0.f;
    for (int i = 0; i < ty; i++) {
        const float2 v = *(const float2*)&g_tilesum[(size_t)(b * NT + i) * SDn + 2 * k2i];
        c0 += v.x; c1 += v.y;
    }

    __half2* zp = (__half2*)g_zh + ((size_t)base * SDn >> 1) + k2i;

    #pragma unroll
    for (int rb = 0; rb < TS; rb += 8) {
        __half2 zv[8];
        #pragma unroll
        for (int q = 0; q < 8; q++) zv[q] = zp[(size_t)q * (SDn / 2)];
        #pragma unroll
        for (int q = 0; q < 8; q++) {
            const int r = rb + q;
            float2 z = __half22float2(zv[q]);
            c0 += z.x;
            c1 += z.y;
            const float inv = __frcp_rn((float)(ty * TS + r + 1));
            __half2 hh = __floats2half2_rn(c0 * inv, c1 * inv);
            zp[(size_t)q * (SDn / 2)] = hh;
            float2 hr = __half22float2(hh);
            float sq = hr.x * hr.x + hr.y * hr.y;
            #pragma unroll
            for (int o = 16; o > 0; o >>= 1) sq += __shfl_xor_sync(0xffffffffu, sq, o);
            if (lane == 0) ssp[r][warp] = sq;
        }
        zp += 8 * (SDn / 2);
    }
    __syncthreads();
    if (threadIdx.x < TS) {
        float s = 0.f;
        #pragma unroll
        for (int w = 0; w < 8; w++) s += ssp[threadIdx.x][w];
        g_rmsinv[base + threadIdx.x] = rsqrtf(s * (1.0f / SDn) + RMS_EPS);
    }
    grid_dep_trigger();
}

// ===========================================================================
// k3b: out = rms_inv[m] * (h @ Wo^T), M=32768, N=1024, K=512 (fp16 inputs)
// ===========================================================================
__global__ void __launch_bounds__(THR, 2) k3b_gemm(float* __restrict__ out) {
    extern __shared__ char smem[];
    const int n0 = blockIdx.x * BN;
    const int m0 = blockIdx.y * BM;
    Frag f;
    gemm_mainloop<SDn>(g_zh, g_wo, m0, n0, smem, f);

    const int t = threadIdx.x;
    const int wid = t >> 5, lane = t & 31;
    const int wm = wid & 1, wn = wid >> 1;
    const int gr = lane >> 2, gc = lane & 3;

    #pragma unroll
    for (int mt = 0; mt < 4; mt++) {
        const int r0 = m0 + wm * 64 + mt * 16 + gr;
        const float ri0 = g_rmsinv[r0];
        const float ri1 = g_rmsinv[r0 + 8];
        #pragma unroll
        for (int nt = 0; nt < 8; nt++) {
            const int col = n0 + wn * 64 + nt * 8 + gc * 2;
            float2 v0 = { f.acc[mt][nt][0] * ri0, f.acc[mt][nt][1] * ri0 };
            float2 v1 = { f.acc[mt][nt][2] * ri1, f.acc[mt][nt][3] * ri1 };
            *(float2*)&out[(size_t)r0 * Dn + col] = v0;
            *(float2*)&out[(size_t)(r0 + 8) * Dn + col] = v1;
        }
    }
}

// ===========================================================================
// host side — single stream; PDL on dependent launches (no allocation)
// ===========================================================================
template <typename... Args>
static void launch_pdl(void (*kern)(Args...), dim3 grid, dim3 block,
                       size_t smem, Args... args) {
    cudaLaunchAttribute attrs[1];
    attrs[0].id = cudaLaunchAttributeProgrammaticStreamSerialization;
    attrs[0].val.programmaticStreamSerializationAllowed = 1;
    cudaLaunchConfig_t cfg{};
    cfg.gridDim = grid;
    cfg.blockDim = block;
    cfg.dynamicSmemBytes = smem;
    cfg.stream = 0;
    cfg.attrs = attrs;
    cfg.numAttrs = 1;
    cudaLaunchKernelEx(&cfg, kern, args...);
}

extern "C" void kernel_launch(void* const* d_in, const int* in_sizes, int n_in,
                              void* d_out, int out_size) {
    const float* x  = (const float*)d_in[0];
    const float* Wu = (const float*)d_in[1];
    const float* Wg = (const float*)d_in[2];
    const float* Wo = (const float*)d_in[3];
    float* out = (float*)d_out;

    cudaFuncSetAttribute(k1_gemm,  cudaFuncAttributeMaxDynamicSharedMemorySize, SMEM_BYTES);
    cudaFuncSetAttribute(k3b_gemm, cudaFuncAttributeMaxDynamicSharedMemorySize, SMEM_BYTES);

    k_cvt_all<<<4096, 256>>>((const float4*)x, (const float4*)Wg,
                             (const float4*)Wu, (const float4*)Wo);
    launch_pdl(k1_gemm, dim3(2 * SDn / BN, Mn / BM), dim3(THR), (size_t)SMEM_BYTES);
    launch_pdl(k3a_scan, dim3(Mn / TS), dim3(256), (size_t)0);
    launch_pdl(k3b_gemm, dim3(Dn / BN, Mn / BM), dim3(THR), (size_t)SMEM_BYTES,
               (float*)out);
}